// round 14
// baseline (speedup 1.0000x reference)
#include <cuda_runtime.h>
#include <cuda_fp16.h>

#define BATCH   8
#define CH      2049          // N/2+1 spectrum bins
#define CHP     2080          // padded half2 row: 2080*4 B = 65*128 (aligned)
#define TFR     345           // frames
#define NFFT    4096
#define MH      2048          // NFFT/2 = complex FFT size
#define HOP     1024
#define NFRAMES (BATCH*TFR)   // 2760

// ---------------- scratch (device globals; no allocations) ----------------
__device__ __half2 g_spec[NFRAMES * CHP];   // [frame][k] = (Re, Im) fp16
__device__ __half  g_frames[NFRAMES * NFFT];// [frame][n] windowed samples (fp16)
__device__ float2  g_twN[MH];               // e^{+2*pi*i*k/4096}
__device__ float2  g_win[MH];               // (hann[2m], hann[2m+1])

// smem bank swizzle (float2 index granularity; 16 float2 = 128B row)
#define SW(p) ((p) ^ (((p) >> 4) & 15))

__device__ __forceinline__ float2 cmul(float2 a, float2 b) {
    return make_float2(a.x*b.x - a.y*b.y, a.x*b.y + a.y*b.x);
}
__device__ __forceinline__ float2 cadd(float2 a, float2 b){ return make_float2(a.x+b.x, a.y+b.y); }
__device__ __forceinline__ float2 csub(float2 a, float2 b){ return make_float2(a.x-b.x, a.y-b.y); }
__device__ __forceinline__ float2 cmuli(float2 a){ return make_float2(-a.y, a.x); }   // i*a

// ---------------- transpose [B, CH, T] -> fp16 g_spec, fused table init -----
// 32k x 64t tile, 32x8 threads (measured-best configuration).
__global__ void __launch_bounds__(256) transpose_kernel(const float* __restrict__ re,
                                                        const float* __restrict__ im)
{
    __shared__ float2 s[32][65];   // fused (re, im) tile, 16.6 KB
    int b  = blockIdx.z;
    int k0 = blockIdx.x << 5, t0 = blockIdx.y << 6;
    int tx = threadIdx.x, ty = threadIdx.y;   // ty in [0,8)

    // fused table init: first 8 (x,0,0) blocks cover 2048 ids
    if (blockIdx.y == 0 && blockIdx.z == 0 && blockIdx.x < 8) {
        int gid = (blockIdx.x << 8) + (ty << 5) + tx;   // 0..2047
        float a = (float)gid * (1.0f / 2048.0f);        // angle in units of pi
        float sv, cv;
        sincospif(a, &sv, &cv);
        g_twN[gid] = make_float2(cv, sv);               // e^{+i*2pi*gid/4096}
        float c0 = cospif((float)(2*gid)     * (1.0f / 2048.0f));
        float c1 = cospif((float)(2*gid + 1) * (1.0f / 2048.0f));
        g_win[gid] = make_float2(0.5f - 0.5f*c0, 0.5f - 0.5f*c1);
    }

    const float* rb = re + (size_t)b * CH * TFR;
    const float* ib = im + (size_t)b * CH * TFR;
    #pragma unroll
    for (int u = 0; u < 2; u++) {
        int t = t0 + tx + (u << 5);
        bool tok = (t < TFR);
        #pragma unroll
        for (int j = 0; j < 4; j++) {
            int kl = ty + (j << 3);
            int k  = k0 + kl;
            if (k < CH && tok)
                s[kl][tx + (u << 5)] = make_float2(__ldcs(rb + k * TFR + t),
                                                   __ldcs(ib + k * TFR + t));
        }
    }
    __syncthreads();
    int ko = k0 + tx;
    bool kok = (ko < CH);
    #pragma unroll
    for (int u = 0; u < 2; u++) {
        #pragma unroll
        for (int j = 0; j < 4; j++) {
            int tl = ty + (j << 3) + (u << 5);
            int to = t0 + tl;
            if (kok && to < TFR) {
                float2 v = s[tx][tl];
                g_spec[((size_t)b * TFR + to) * CHP + ko] = __floats2half2_rn(v.x, v.y);
            }
        }
    }
}

// ---------------- 16-point inverse DFT in registers (e^{+} convention) ------
__device__ __forceinline__ void idft16(float2* x)
{
    const float R  = 0.70710678118654752440f;  // sqrt(2)/2
    const float C1 = 0.92387953251128675613f;  // cos(pi/8)
    const float S1 = 0.38268343236508977173f;  // sin(pi/8)

    float2 t[16];   // t[p2*4 + q1] = IDFT4 over p1 of x[4*p1 + p2]
    #pragma unroll
    for (int p2 = 0; p2 < 4; p2++) {
        float2 a = x[p2], b = x[4+p2], c = x[8+p2], d = x[12+p2];
        float2 u0 = cadd(a,c), u1 = csub(a,c);
        float2 u2 = cadd(b,d), u3 = cmuli(csub(b,d));
        t[p2*4+0] = cadd(u0,u2);
        t[p2*4+1] = cadd(u1,u3);
        t[p2*4+2] = csub(u0,u2);
        t[p2*4+3] = csub(u1,u3);
    }
    {
        float2 t0=t[0], t1=t[4], t2=t[8], t3=t[12];
        float2 u0=cadd(t0,t2), u1=csub(t0,t2), u2=cadd(t1,t3), u3=cmuli(csub(t1,t3));
        x[0]=cadd(u0,u2); x[4]=cadd(u1,u3); x[8]=csub(u0,u2); x[12]=csub(u1,u3);
    }
    {
        float2 t0=t[1];
        float2 t1=cmul(t[5],  make_float2(C1, S1));
        float2 a2=t[9];  float2 t2=make_float2(R*(a2.x-a2.y), R*(a2.x+a2.y));
        float2 t3=cmul(t[13], make_float2(S1, C1));
        float2 u0=cadd(t0,t2), u1=csub(t0,t2), u2=cadd(t1,t3), u3=cmuli(csub(t1,t3));
        x[1]=cadd(u0,u2); x[5]=cadd(u1,u3); x[9]=csub(u0,u2); x[13]=csub(u1,u3);
    }
    {
        float2 t0=t[2];
        float2 a1=t[6];  float2 t1=make_float2(R*(a1.x-a1.y), R*(a1.x+a1.y));
        float2 t2=cmuli(t[10]);
        float2 t3=cmul(t[14], make_float2(-R, R));
        float2 u0=cadd(t0,t2), u1=csub(t0,t2), u2=cadd(t1,t3), u3=cmuli(csub(t1,t3));
        x[2]=cadd(u0,u2); x[6]=cadd(u1,u3); x[10]=csub(u0,u2); x[14]=csub(u1,u3);
    }
    {
        float2 t0=t[3];
        float2 t1=cmul(t[7],  make_float2(S1, C1));
        float2 t2=cmul(t[11], make_float2(-R, R));
        float2 t3=cmul(t[15], make_float2(-C1, -S1));
        float2 u0=cadd(t0,t2), u1=csub(t0,t2), u2=cadd(t1,t3), u3=cmuli(csub(t1,t3));
        x[3]=cadd(u0,u2); x[7]=cadd(u1,u3); x[11]=csub(u0,u2); x[15]=csub(u1,u3);
    }
}

// ---------------- in-place radix-16 Stockham DIF pass (inverse) --------------
__device__ __forceinline__ void radix16_pass(float2* __restrict__ buf,
                                             const float2* __restrict__ tws,
                                             int tid, int m)
{
    int jm = tid & ~(m - 1);
    float2 x[16];
    #pragma unroll
    for (int q = 0; q < 16; q++) x[q] = buf[SW(tid + (q << 7))];
    float2 w1 = tws[jm];          // W_2048^{jm}, jm <= 127 for both passes
    __syncthreads();

    idft16(x);

    int base = tid + 15 * jm;     // = 16*jm + i
    buf[SW(base)] = x[0];
    float2 w = w1;
    buf[SW(base + m)] = cmul(x[1], w);
    #pragma unroll
    for (int q = 2; q < 16; q++) {
        w = cmul(w, w1);
        buf[SW(base + q * m)] = cmul(x[q], w);
    }
    __syncthreads();
}

// ---------------- per-frame inverse real FFT (size 4096) ---------------------
// Half-size packing -> IDFT_2048 via radix 16*16*8 (final stage twiddle-free).
__global__ void __launch_bounds__(128) ifft_kernel()
{
    __shared__ float2 buf[MH];     // in-place working buffer (16 KB)
    __shared__ float2 tws[128];    // W_2048^r, r in [0,128)

    int f   = blockIdx.x;
    int tid = threadIdx.x;         // 0..127
    const __half2* __restrict__ X = g_spec + (size_t)f * CHP;

#if __CUDA_ARCH__ >= 900
    cudaGridDependencySynchronize();   // wait for transpose output (PDL)
#endif

    tws[tid] = g_twN[2 * tid];

    const float sc = 1.0f / 256.0f;
    #pragma unroll
    for (int j = 0; j < 16; j++) {
        int k = tid + (j << 7);
        float2 Xk = __half22float2(__ldcs(X + k));        // read-once stream
        float2 Xc = __half22float2(__ldcs(X + (MH - k))); // read-once stream
        if (k == 0) { Xk.y = 0.f; Xc.y = 0.f; }
        float ex = sc * (Xk.x + Xc.x);
        float ey = sc * (Xk.y - Xc.y);
        float dx = sc * (Xk.x - Xc.x);
        float dy = sc * (Xk.y + Xc.y);
        float2 w = g_twN[k];
        float ox = dx * w.x - dy * w.y;
        float oy = dx * w.y + dy * w.x;
        buf[SW(k)] = make_float2(ex - oy, ey + ox);
    }
    __syncthreads();

    radix16_pass(buf, tws, tid, 1);    // m = 1
    radix16_pass(buf, tws, tid, 16);   // m = 16

    // final radix-8 pass: m=256 -> single j-group, twiddle-free; fused window
    __half2* __restrict__ fr = (__half2*)(g_frames + (size_t)f * NFFT);
    #pragma unroll
    for (int h = 0; h < 2; h++) {
        int idx = tid + (h << 7);      // butterfly index in [0,256)
        float2 x0 = buf[SW(idx       )];
        float2 x1 = buf[SW(idx +  256)];
        float2 x2 = buf[SW(idx +  512)];
        float2 x3 = buf[SW(idx +  768)];
        float2 x4 = buf[SW(idx + 1024)];
        float2 x5 = buf[SW(idx + 1280)];
        float2 x6 = buf[SW(idx + 1536)];
        float2 x7 = buf[SW(idx + 1792)];

        float2 ta = cadd(x0, x4), tb = csub(x0, x4);
        float2 tc = cadd(x2, x6), td = cmuli(csub(x2, x6));
        float2 E0 = cadd(ta, tc), E1 = cadd(tb, td);
        float2 E2 = csub(ta, tc), E3 = csub(tb, td);
        float2 sa = cadd(x1, x5), sb = csub(x1, x5);
        float2 scc = cadd(x3, x7), sd = cmuli(csub(x3, x7));
        float2 O0 = cadd(sa, scc), O1 = cadd(sb, sd);
        float2 O2 = csub(sa, scc), O3 = csub(sb, sd);
        const float R = 0.70710678118654752440f;
        O1 = make_float2(R*(O1.x - O1.y), R*(O1.x + O1.y));
        O2 = cmuli(O2);
        O3 = make_float2(R*(-O3.x - O3.y), R*(O3.x - O3.y));

        float2 y[8];
        y[0] = cadd(E0, O0); y[4] = csub(E0, O0);
        y[1] = cadd(E1, O1); y[5] = csub(E1, O1);
        y[2] = cadd(E2, O2); y[6] = csub(E2, O2);
        y[3] = cadd(E3, O3); y[7] = csub(E3, O3);

        #pragma unroll
        for (int q = 0; q < 8; q++) {
            int n = idx + (q << 8);
            float2 w = g_win[n];
            fr[n] = __floats2half2_rn(y[q].x * w.x, y[q].y * w.y);
        }
    }
}

// ---------------- gather overlap-add (fp16 frames -> fp32), 8 samples/thread -
__global__ void __launch_bounds__(128) ola_kernel(const float* __restrict__ wsi,
                                                  float* __restrict__ out, int outlen)
{
    int s = blockIdx.x;                // 1024-sample output segment
    int b = blockIdx.y;
    int r = threadIdx.x << 3;          // 0..1016, 8 halves (16B) per thread
    int j = (s << 10) + r;
    if (j + 8 > outlen) return;        // outlen divisible by 8 -> exact cover
    int p   = j + MH;                  // position in padded signal (skip N/2)
    int seg = p >> 10;                 // = s + 2

    // wsi is an input (independent of ifft) -> prefetch before the PDL sync
    float4 w0 = __ldcs((const float4*)(wsi + p));
    float4 w1 = __ldcs((const float4*)(wsi + p + 4));

#if __CUDA_ARCH__ >= 900
    cudaGridDependencySynchronize();   // wait for ifft frames (PDL)
#endif

    const __half* frbase = g_frames + (size_t)b * TFR * NFFT;
    float acc[8] = {0,0,0,0,0,0,0,0};
    #pragma unroll
    for (int d = 0; d < 4; d++) {
        int t = seg - d;
        if (t >= 0 && t < TFR) {
            uint4 raw = __ldcs((const uint4*)(frbase + (size_t)t * NFFT + r + (d << 10)));
            float2 v;
            v = __half22float2(*(__half2*)&raw.x); acc[0] += v.x; acc[1] += v.y;
            v = __half22float2(*(__half2*)&raw.y); acc[2] += v.x; acc[3] += v.y;
            v = __half22float2(*(__half2*)&raw.z); acc[4] += v.x; acc[5] += v.y;
            v = __half22float2(*(__half2*)&raw.w); acc[6] += v.x; acc[7] += v.y;
        }
    }
    float* op = out + (size_t)b * outlen + j;
    float4 o0 = make_float4(acc[0]*w0.x, acc[1]*w0.y, acc[2]*w0.z, acc[3]*w0.w);
    float4 o1 = make_float4(acc[4]*w1.x, acc[5]*w1.y, acc[6]*w1.z, acc[7]*w1.w);
    __stcs((float4*)(op),     o0);     // streaming store: out is never re-read
    __stcs((float4*)(op + 4), o1);
}

// ---------------- launch -----------------------------------------------------
extern "C" void kernel_launch(void* const* d_in, const int* in_sizes, int n_in,
                              void* d_out, int out_size)
{
    const float* re  = (const float*)d_in[0];
    const float* im  = (const float*)d_in[1];
    // d_in[2] = inverse_basis (unused: replaced analytically by the iFFT)
    const float* wsi = (const float*)d_in[3];
    float* out = (float*)d_out;
    int outlen = out_size / BATCH;     // 352800

    dim3 tgrid((CH + 31) / 32, (TFR + 63) / 64, BATCH);
    transpose_kernel<<<tgrid, dim3(32, 8)>>>(re, im);

    cudaLaunchAttribute attr[1];
    attr[0].id = cudaLaunchAttributeProgrammaticStreamSerialization;
    attr[0].val.programmaticStreamSerializationAllowed = 1;

    cudaLaunchConfig_t cfg1 = {};
    cfg1.gridDim = dim3(NFRAMES); cfg1.blockDim = dim3(128);
    cfg1.dynamicSmemBytes = 0; cfg1.stream = 0;
    cfg1.attrs = attr; cfg1.numAttrs = 1;
    if (cudaLaunchKernelEx(&cfg1, ifft_kernel) != cudaSuccess)
        ifft_kernel<<<NFRAMES, 128>>>();

    cudaLaunchConfig_t cfg2 = {};
    cfg2.gridDim = dim3((outlen + 1023) / 1024, BATCH); cfg2.blockDim = dim3(128);
    cfg2.dynamicSmemBytes = 0; cfg2.stream = 0;
    cfg2.attrs = attr; cfg2.numAttrs = 1;
    if (cudaLaunchKernelEx(&cfg2, ola_kernel, wsi, out, outlen) != cudaSuccess)
        ola_kernel<<<dim3((outlen + 1023) / 1024, BATCH), 128>>>(wsi, out, outlen);
}

// round 15
// speedup vs baseline: 1.0331x; 1.0331x over previous
#include <cuda_runtime.h>
#include <cuda_fp16.h>

#define BATCH   8
#define CH      2049          // N/2+1 spectrum bins
#define CHP     2080          // padded half2 row: 2080*4 B = 65*128 (aligned)
#define TFR     345           // frames
#define NFFT    4096
#define MH      2048          // NFFT/2 = complex FFT size
#define HOP     1024
#define NFRAMES (BATCH*TFR)   // 2760

// ---------------- scratch (device globals; no allocations) ----------------
__device__ __half2 g_spec[NFRAMES * CHP];   // [frame][k] = (Re, Im) fp16
__device__ __half  g_frames[NFRAMES * NFFT];// [frame][n] windowed samples (fp16)
__device__ float2  g_twN[MH];               // e^{+2*pi*i*k/4096}
__device__ float2  g_win[MH];               // (hann[2m], hann[2m+1])

// smem bank swizzle (float2 index granularity; 16 float2 = 128B row)
#define SW(p) ((p) ^ (((p) >> 4) & 15))

__device__ __forceinline__ float2 cmul(float2 a, float2 b) {
    return make_float2(a.x*b.x - a.y*b.y, a.x*b.y + a.y*b.x);
}
__device__ __forceinline__ float2 cadd(float2 a, float2 b){ return make_float2(a.x+b.x, a.y+b.y); }
__device__ __forceinline__ float2 csub(float2 a, float2 b){ return make_float2(a.x-b.x, a.y-b.y); }
__device__ __forceinline__ float2 cmuli(float2 a){ return make_float2(-a.y, a.x); }   // i*a

// ---------------- transpose [B, CH, T] -> fp16 g_spec, fused table init -----
// 32k x 64t tile, 32x8 threads (measured-best configuration).
__global__ void __launch_bounds__(256) transpose_kernel(const float* __restrict__ re,
                                                        const float* __restrict__ im)
{
    __shared__ float2 s[32][65];   // fused (re, im) tile, 16.6 KB
    int b  = blockIdx.z;
    int k0 = blockIdx.x << 5, t0 = blockIdx.y << 6;
    int tx = threadIdx.x, ty = threadIdx.y;   // ty in [0,8)

    // fused table init: first 8 (x,0,0) blocks cover 2048 ids
    if (blockIdx.y == 0 && blockIdx.z == 0 && blockIdx.x < 8) {
        int gid = (blockIdx.x << 8) + (ty << 5) + tx;   // 0..2047
        float a = (float)gid * (1.0f / 2048.0f);        // angle in units of pi
        float sv, cv;
        sincospif(a, &sv, &cv);
        g_twN[gid] = make_float2(cv, sv);               // e^{+i*2pi*gid/4096}
        float c0 = cospif((float)(2*gid)     * (1.0f / 2048.0f));
        float c1 = cospif((float)(2*gid + 1) * (1.0f / 2048.0f));
        g_win[gid] = make_float2(0.5f - 0.5f*c0, 0.5f - 0.5f*c1);
    }

    const float* rb = re + (size_t)b * CH * TFR;
    const float* ib = im + (size_t)b * CH * TFR;
    #pragma unroll
    for (int u = 0; u < 2; u++) {
        int t = t0 + tx + (u << 5);
        bool tok = (t < TFR);
        #pragma unroll
        for (int j = 0; j < 4; j++) {
            int kl = ty + (j << 3);
            int k  = k0 + kl;
            if (k < CH && tok)
                s[kl][tx + (u << 5)] = make_float2(__ldcs(rb + k * TFR + t),
                                                   __ldcs(ib + k * TFR + t));
        }
    }
    __syncthreads();
    int ko = k0 + tx;
    bool kok = (ko < CH);
    #pragma unroll
    for (int u = 0; u < 2; u++) {
        #pragma unroll
        for (int j = 0; j < 4; j++) {
            int tl = ty + (j << 3) + (u << 5);
            int to = t0 + tl;
            if (kok && to < TFR) {
                float2 v = s[tx][tl];
                g_spec[((size_t)b * TFR + to) * CHP + ko] = __floats2half2_rn(v.x, v.y);
            }
        }
    }
}

// ---------------- 16-point inverse DFT in registers (e^{+} convention) ------
__device__ __forceinline__ void idft16(float2* x)
{
    const float R  = 0.70710678118654752440f;  // sqrt(2)/2
    const float C1 = 0.92387953251128675613f;  // cos(pi/8)
    const float S1 = 0.38268343236508977173f;  // sin(pi/8)

    float2 t[16];   // t[p2*4 + q1] = IDFT4 over p1 of x[4*p1 + p2]
    #pragma unroll
    for (int p2 = 0; p2 < 4; p2++) {
        float2 a = x[p2], b = x[4+p2], c = x[8+p2], d = x[12+p2];
        float2 u0 = cadd(a,c), u1 = csub(a,c);
        float2 u2 = cadd(b,d), u3 = cmuli(csub(b,d));
        t[p2*4+0] = cadd(u0,u2);
        t[p2*4+1] = cadd(u1,u3);
        t[p2*4+2] = csub(u0,u2);
        t[p2*4+3] = csub(u1,u3);
    }
    {
        float2 t0=t[0], t1=t[4], t2=t[8], t3=t[12];
        float2 u0=cadd(t0,t2), u1=csub(t0,t2), u2=cadd(t1,t3), u3=cmuli(csub(t1,t3));
        x[0]=cadd(u0,u2); x[4]=cadd(u1,u3); x[8]=csub(u0,u2); x[12]=csub(u1,u3);
    }
    {
        float2 t0=t[1];
        float2 t1=cmul(t[5],  make_float2(C1, S1));
        float2 a2=t[9];  float2 t2=make_float2(R*(a2.x-a2.y), R*(a2.x+a2.y));
        float2 t3=cmul(t[13], make_float2(S1, C1));
        float2 u0=cadd(t0,t2), u1=csub(t0,t2), u2=cadd(t1,t3), u3=cmuli(csub(t1,t3));
        x[1]=cadd(u0,u2); x[5]=cadd(u1,u3); x[9]=csub(u0,u2); x[13]=csub(u1,u3);
    }
    {
        float2 t0=t[2];
        float2 a1=t[6];  float2 t1=make_float2(R*(a1.x-a1.y), R*(a1.x+a1.y));
        float2 t2=cmuli(t[10]);
        float2 t3=cmul(t[14], make_float2(-R, R));
        float2 u0=cadd(t0,t2), u1=csub(t0,t2), u2=cadd(t1,t3), u3=cmuli(csub(t1,t3));
        x[2]=cadd(u0,u2); x[6]=cadd(u1,u3); x[10]=csub(u0,u2); x[14]=csub(u1,u3);
    }
    {
        float2 t0=t[3];
        float2 t1=cmul(t[7],  make_float2(S1, C1));
        float2 t2=cmul(t[11], make_float2(-R, R));
        float2 t3=cmul(t[15], make_float2(-C1, -S1));
        float2 u0=cadd(t0,t2), u1=csub(t0,t2), u2=cadd(t1,t3), u3=cmuli(csub(t1,t3));
        x[3]=cadd(u0,u2); x[7]=cadd(u1,u3); x[11]=csub(u0,u2); x[15]=csub(u1,u3);
    }
}

// ---------------- in-place radix-16 Stockham DIF pass (inverse) --------------
__device__ __forceinline__ void radix16_pass(float2* __restrict__ buf,
                                             const float2* __restrict__ tws,
                                             int tid, int m)
{
    int jm = tid & ~(m - 1);
    float2 x[16];
    #pragma unroll
    for (int q = 0; q < 16; q++) x[q] = buf[SW(tid + (q << 7))];
    float2 w1 = tws[jm];          // W_2048^{jm}, jm <= 127 for both passes
    __syncthreads();

    idft16(x);

    int base = tid + 15 * jm;     // = 16*jm + i
    buf[SW(base)] = x[0];
    float2 w = w1;
    buf[SW(base + m)] = cmul(x[1], w);
    #pragma unroll
    for (int q = 2; q < 16; q++) {
        w = cmul(w, w1);
        buf[SW(base + q * m)] = cmul(x[q], w);
    }
    __syncthreads();
}

// ---------------- per-frame inverse real FFT (size 4096) ---------------------
// Half-size packing -> IDFT_2048 via radix 16*16*8 (final stage twiddle-free).
__global__ void __launch_bounds__(128) ifft_kernel()
{
    __shared__ float2 buf[MH];     // in-place working buffer (16 KB)
    __shared__ float2 tws[128];    // W_2048^r, r in [0,128)

    int f   = blockIdx.x;
    int tid = threadIdx.x;         // 0..127
    const __half2* __restrict__ X = g_spec + (size_t)f * CHP;

#if __CUDA_ARCH__ >= 900
    cudaGridDependencySynchronize();   // wait for transpose output (PDL)
#endif

    tws[tid] = g_twN[2 * tid];

    const float sc = 1.0f / 256.0f;
    #pragma unroll
    for (int j = 0; j < 16; j++) {
        int k = tid + (j << 7);
        float2 Xk = __half22float2(X[k]);        // read 2x per block -> default policy
        float2 Xc = __half22float2(X[MH - k]);
        if (k == 0) { Xk.y = 0.f; Xc.y = 0.f; }
        float ex = sc * (Xk.x + Xc.x);
        float ey = sc * (Xk.y - Xc.y);
        float dx = sc * (Xk.x - Xc.x);
        float dy = sc * (Xk.y + Xc.y);
        float2 w = g_twN[k];
        float ox = dx * w.x - dy * w.y;
        float oy = dx * w.y + dy * w.x;
        buf[SW(k)] = make_float2(ex - oy, ey + ox);
    }
    __syncthreads();

    radix16_pass(buf, tws, tid, 1);    // m = 1
    radix16_pass(buf, tws, tid, 16);   // m = 16

    // final radix-8 pass: m=256 -> single j-group, twiddle-free; fused window
    __half2* __restrict__ fr = (__half2*)(g_frames + (size_t)f * NFFT);
    #pragma unroll
    for (int h = 0; h < 2; h++) {
        int idx = tid + (h << 7);      // butterfly index in [0,256)
        float2 x0 = buf[SW(idx       )];
        float2 x1 = buf[SW(idx +  256)];
        float2 x2 = buf[SW(idx +  512)];
        float2 x3 = buf[SW(idx +  768)];
        float2 x4 = buf[SW(idx + 1024)];
        float2 x5 = buf[SW(idx + 1280)];
        float2 x6 = buf[SW(idx + 1536)];
        float2 x7 = buf[SW(idx + 1792)];

        float2 ta = cadd(x0, x4), tb = csub(x0, x4);
        float2 tc = cadd(x2, x6), td = cmuli(csub(x2, x6));
        float2 E0 = cadd(ta, tc), E1 = cadd(tb, td);
        float2 E2 = csub(ta, tc), E3 = csub(tb, td);
        float2 sa = cadd(x1, x5), sb = csub(x1, x5);
        float2 scc = cadd(x3, x7), sd = cmuli(csub(x3, x7));
        float2 O0 = cadd(sa, scc), O1 = cadd(sb, sd);
        float2 O2 = csub(sa, scc), O3 = csub(sb, sd);
        const float R = 0.70710678118654752440f;
        O1 = make_float2(R*(O1.x - O1.y), R*(O1.x + O1.y));
        O2 = cmuli(O2);
        O3 = make_float2(R*(-O3.x - O3.y), R*(O3.x - O3.y));

        float2 y[8];
        y[0] = cadd(E0, O0); y[4] = csub(E0, O0);
        y[1] = cadd(E1, O1); y[5] = csub(E1, O1);
        y[2] = cadd(E2, O2); y[6] = csub(E2, O2);
        y[3] = cadd(E3, O3); y[7] = csub(E3, O3);

        #pragma unroll
        for (int q = 0; q < 8; q++) {
            int n = idx + (q << 8);
            float2 w = g_win[n];
            fr[n] = __floats2half2_rn(y[q].x * w.x, y[q].y * w.y);
        }
    }
}

// ---------------- gather overlap-add (fp16 frames -> fp32), 8 samples/thread -
__global__ void __launch_bounds__(128) ola_kernel(const float* __restrict__ wsi,
                                                  float* __restrict__ out, int outlen)
{
    int s = blockIdx.x;                // 1024-sample output segment
    int b = blockIdx.y;
    int r = threadIdx.x << 3;          // 0..1016, 8 halves (16B) per thread
    int j = (s << 10) + r;
    if (j + 8 > outlen) return;        // outlen divisible by 8 -> exact cover
    int p   = j + MH;                  // position in padded signal (skip N/2)
    int seg = p >> 10;                 // = s + 2

    // wsi is shared across all 8 batch rows -> default policy (L2 reuse)
    float4 w0 = *(const float4*)(wsi + p);
    float4 w1 = *(const float4*)(wsi + p + 4);

#if __CUDA_ARCH__ >= 900
    cudaGridDependencySynchronize();   // wait for ifft frames (PDL)
#endif

    const __half* frbase = g_frames + (size_t)b * TFR * NFFT;
    float acc[8] = {0,0,0,0,0,0,0,0};
    #pragma unroll
    for (int d = 0; d < 4; d++) {
        int t = seg - d;
        if (t >= 0 && t < TFR) {
            // each frames element consumed exactly once grid-wide -> evict-first
            uint4 raw = __ldcs((const uint4*)(frbase + (size_t)t * NFFT + r + (d << 10)));
            float2 v;
            v = __half22float2(*(__half2*)&raw.x); acc[0] += v.x; acc[1] += v.y;
            v = __half22float2(*(__half2*)&raw.y); acc[2] += v.x; acc[3] += v.y;
            v = __half22float2(*(__half2*)&raw.z); acc[4] += v.x; acc[5] += v.y;
            v = __half22float2(*(__half2*)&raw.w); acc[6] += v.x; acc[7] += v.y;
        }
    }
    float* op = out + (size_t)b * outlen + j;
    float4 o0 = make_float4(acc[0]*w0.x, acc[1]*w0.y, acc[2]*w0.z, acc[3]*w0.w);
    float4 o1 = make_float4(acc[4]*w1.x, acc[5]*w1.y, acc[6]*w1.z, acc[7]*w1.w);
    __stcs((float4*)(op),     o0);     // streaming store: out is never re-read
    __stcs((float4*)(op + 4), o1);
}

// ---------------- launch -----------------------------------------------------
extern "C" void kernel_launch(void* const* d_in, const int* in_sizes, int n_in,
                              void* d_out, int out_size)
{
    const float* re  = (const float*)d_in[0];
    const float* im  = (const float*)d_in[1];
    // d_in[2] = inverse_basis (unused: replaced analytically by the iFFT)
    const float* wsi = (const float*)d_in[3];
    float* out = (float*)d_out;
    int outlen = out_size / BATCH;     // 352800

    dim3 tgrid((CH + 31) / 32, (TFR + 63) / 64, BATCH);
    transpose_kernel<<<tgrid, dim3(32, 8)>>>(re, im);

    cudaLaunchAttribute attr[1];
    attr[0].id = cudaLaunchAttributeProgrammaticStreamSerialization;
    attr[0].val.programmaticStreamSerializationAllowed = 1;

    cudaLaunchConfig_t cfg1 = {};
    cfg1.gridDim = dim3(NFRAMES); cfg1.blockDim = dim3(128);
    cfg1.dynamicSmemBytes = 0; cfg1.stream = 0;
    cfg1.attrs = attr; cfg1.numAttrs = 1;
    if (cudaLaunchKernelEx(&cfg1, ifft_kernel) != cudaSuccess)
        ifft_kernel<<<NFRAMES, 128>>>();

    cudaLaunchConfig_t cfg2 = {};
    cfg2.gridDim = dim3((outlen + 1023) / 1024, BATCH); cfg2.blockDim = dim3(128);
    cfg2.dynamicSmemBytes = 0; cfg2.stream = 0;
    cfg2.attrs = attr; cfg2.numAttrs = 1;
    if (cudaLaunchKernelEx(&cfg2, ola_kernel, wsi, out, outlen) != cudaSuccess)
        ola_kernel<<<dim3((outlen + 1023) / 1024, BATCH), 128>>>(wsi, out, outlen);
}

// round 16
// speedup vs baseline: 1.0407x; 1.0073x over previous
#include <cuda_runtime.h>
#include <cuda_fp16.h>

#define BATCH   8
#define CH      2049          // N/2+1 spectrum bins
#define CHP     2080          // padded half2 row: 2080*4 B = 65*128 (aligned)
#define TFR     345           // frames
#define NFFT    4096
#define MH      2048          // NFFT/2 = complex FFT size
#define HOP     1024
#define NFRAMES (BATCH*TFR)   // 2760

// ---------------- scratch (device globals; no allocations) ----------------
__device__ __half2 g_spec[NFRAMES * CHP];   // [frame][k] = (Re, Im) fp16
__device__ __half  g_frames[NFRAMES * NFFT];// [frame][n] windowed samples (fp16)
__device__ float2  g_twN[MH];               // e^{+2*pi*i*k/4096}
__device__ float2  g_win[MH];               // (hann[2m], hann[2m+1])

// smem bank swizzle (float2 index granularity; 16 float2 = 128B row)
#define SW(p) ((p) ^ (((p) >> 4) & 15))

__device__ __forceinline__ float2 cmul(float2 a, float2 b) {
    return make_float2(a.x*b.x - a.y*b.y, a.x*b.y + a.y*b.x);
}
__device__ __forceinline__ float2 cadd(float2 a, float2 b){ return make_float2(a.x+b.x, a.y+b.y); }
__device__ __forceinline__ float2 csub(float2 a, float2 b){ return make_float2(a.x-b.x, a.y-b.y); }
__device__ __forceinline__ float2 cmuli(float2 a){ return make_float2(-a.y, a.x); }   // i*a

// ---------------- transpose [B, CH, T] -> fp16 g_spec, fused table init -----
// 32k x 64t tile, 32x8 threads (measured-best configuration).
__global__ void __launch_bounds__(256) transpose_kernel(const float* __restrict__ re,
                                                        const float* __restrict__ im)
{
    __shared__ float2 s[32][65];   // fused (re, im) tile, 16.6 KB
    int b  = blockIdx.z;
    int k0 = blockIdx.x << 5, t0 = blockIdx.y << 6;
    int tx = threadIdx.x, ty = threadIdx.y;   // ty in [0,8)

    // fused table init: first 8 (x,0,0) blocks cover 2048 ids
    if (blockIdx.y == 0 && blockIdx.z == 0 && blockIdx.x < 8) {
        int gid = (blockIdx.x << 8) + (ty << 5) + tx;   // 0..2047
        float a = (float)gid * (1.0f / 2048.0f);        // angle in units of pi
        float sv, cv;
        sincospif(a, &sv, &cv);
        g_twN[gid] = make_float2(cv, sv);               // e^{+i*2pi*gid/4096}
        float c0 = cospif((float)(2*gid)     * (1.0f / 2048.0f));
        float c1 = cospif((float)(2*gid + 1) * (1.0f / 2048.0f));
        g_win[gid] = make_float2(0.5f - 0.5f*c0, 0.5f - 0.5f*c1);
    }

    const float* rb = re + (size_t)b * CH * TFR;
    const float* ib = im + (size_t)b * CH * TFR;
    #pragma unroll
    for (int u = 0; u < 2; u++) {
        int t = t0 + tx + (u << 5);
        bool tok = (t < TFR);
        #pragma unroll
        for (int j = 0; j < 4; j++) {
            int kl = ty + (j << 3);
            int k  = k0 + kl;
            if (k < CH && tok)
                s[kl][tx + (u << 5)] = make_float2(__ldcs(rb + k * TFR + t),
                                                   __ldcs(ib + k * TFR + t));
        }
    }
    __syncthreads();
    int ko = k0 + tx;
    bool kok = (ko < CH);
    #pragma unroll
    for (int u = 0; u < 2; u++) {
        #pragma unroll
        for (int j = 0; j < 4; j++) {
            int tl = ty + (j << 3) + (u << 5);
            int to = t0 + tl;
            if (kok && to < TFR) {
                float2 v = s[tx][tl];
                g_spec[((size_t)b * TFR + to) * CHP + ko] = __floats2half2_rn(v.x, v.y);
            }
        }
    }
}

// ---------------- 16-point inverse DFT in registers (e^{+} convention) ------
__device__ __forceinline__ void idft16(float2* x)
{
    const float R  = 0.70710678118654752440f;  // sqrt(2)/2
    const float C1 = 0.92387953251128675613f;  // cos(pi/8)
    const float S1 = 0.38268343236508977173f;  // sin(pi/8)

    float2 t[16];   // t[p2*4 + q1] = IDFT4 over p1 of x[4*p1 + p2]
    #pragma unroll
    for (int p2 = 0; p2 < 4; p2++) {
        float2 a = x[p2], b = x[4+p2], c = x[8+p2], d = x[12+p2];
        float2 u0 = cadd(a,c), u1 = csub(a,c);
        float2 u2 = cadd(b,d), u3 = cmuli(csub(b,d));
        t[p2*4+0] = cadd(u0,u2);
        t[p2*4+1] = cadd(u1,u3);
        t[p2*4+2] = csub(u0,u2);
        t[p2*4+3] = csub(u1,u3);
    }
    {
        float2 t0=t[0], t1=t[4], t2=t[8], t3=t[12];
        float2 u0=cadd(t0,t2), u1=csub(t0,t2), u2=cadd(t1,t3), u3=cmuli(csub(t1,t3));
        x[0]=cadd(u0,u2); x[4]=cadd(u1,u3); x[8]=csub(u0,u2); x[12]=csub(u1,u3);
    }
    {
        float2 t0=t[1];
        float2 t1=cmul(t[5],  make_float2(C1, S1));
        float2 a2=t[9];  float2 t2=make_float2(R*(a2.x-a2.y), R*(a2.x+a2.y));
        float2 t3=cmul(t[13], make_float2(S1, C1));
        float2 u0=cadd(t0,t2), u1=csub(t0,t2), u2=cadd(t1,t3), u3=cmuli(csub(t1,t3));
        x[1]=cadd(u0,u2); x[5]=cadd(u1,u3); x[9]=csub(u0,u2); x[13]=csub(u1,u3);
    }
    {
        float2 t0=t[2];
        float2 a1=t[6];  float2 t1=make_float2(R*(a1.x-a1.y), R*(a1.x+a1.y));
        float2 t2=cmuli(t[10]);
        float2 t3=cmul(t[14], make_float2(-R, R));
        float2 u0=cadd(t0,t2), u1=csub(t0,t2), u2=cadd(t1,t3), u3=cmuli(csub(t1,t3));
        x[2]=cadd(u0,u2); x[6]=cadd(u1,u3); x[10]=csub(u0,u2); x[14]=csub(u1,u3);
    }
    {
        float2 t0=t[3];
        float2 t1=cmul(t[7],  make_float2(S1, C1));
        float2 t2=cmul(t[11], make_float2(-R, R));
        float2 t3=cmul(t[15], make_float2(-C1, -S1));
        float2 u0=cadd(t0,t2), u1=csub(t0,t2), u2=cadd(t1,t3), u3=cmuli(csub(t1,t3));
        x[3]=cadd(u0,u2); x[7]=cadd(u1,u3); x[11]=csub(u0,u2); x[15]=csub(u1,u3);
    }
}

// ---------------- in-place radix-16 Stockham DIF pass (inverse) --------------
// Twiddle powers via breadth-first tree (depth 4, was a 15-deep serial chain);
// stores issue in power-availability order (output order is irrelevant).
__device__ __forceinline__ void radix16_pass(float2* __restrict__ buf,
                                             const float2* __restrict__ tws,
                                             int tid, int m)
{
    int jm = tid & ~(m - 1);
    float2 x[16];
    #pragma unroll
    for (int q = 0; q < 16; q++) x[q] = buf[SW(tid + (q << 7))];
    float2 w1 = tws[jm];          // W_2048^{jm}, jm <= 127 for both passes
    __syncthreads();

    idft16(x);

    int base = tid + 15 * jm;     // = 16*jm + i
    buf[SW(base)] = x[0];
    buf[SW(base + m)] = cmul(x[1], w1);
    float2 w2 = cmul(w1, w1);
    buf[SW(base +  2*m)] = cmul(x[2],  w2);
    float2 w4 = cmul(w2, w2);
    buf[SW(base +  4*m)] = cmul(x[4],  w4);
    float2 w3 = cmul(w2, w1);
    buf[SW(base +  3*m)] = cmul(x[3],  w3);
    float2 w8 = cmul(w4, w4);
    buf[SW(base +  8*m)] = cmul(x[8],  w8);
    float2 w5 = cmul(w4, w1);
    buf[SW(base +  5*m)] = cmul(x[5],  w5);
    float2 w6 = cmul(w4, w2);
    buf[SW(base +  6*m)] = cmul(x[6],  w6);
    float2 w7 = cmul(w4, w3);
    buf[SW(base +  7*m)] = cmul(x[7],  w7);
    buf[SW(base +  9*m)] = cmul(x[9],  cmul(w8, w1));
    buf[SW(base + 10*m)] = cmul(x[10], cmul(w8, w2));
    buf[SW(base + 11*m)] = cmul(x[11], cmul(w8, w3));
    buf[SW(base + 12*m)] = cmul(x[12], cmul(w8, w4));
    buf[SW(base + 13*m)] = cmul(x[13], cmul(w8, w5));
    buf[SW(base + 14*m)] = cmul(x[14], cmul(w8, w6));
    buf[SW(base + 15*m)] = cmul(x[15], cmul(w8, w7));
    __syncthreads();
}

// ---------------- per-frame inverse real FFT (size 4096) ---------------------
// Half-size packing -> IDFT_2048 via radix 16*16*8 (final stage twiddle-free).
__global__ void __launch_bounds__(128) ifft_kernel()
{
    __shared__ float2 buf[MH];     // in-place working buffer (16 KB)
    __shared__ float2 tws[128];    // W_2048^r, r in [0,128)

    int f   = blockIdx.x;
    int tid = threadIdx.x;         // 0..127
    const __half2* __restrict__ X = g_spec + (size_t)f * CHP;

#if __CUDA_ARCH__ >= 900
    cudaGridDependencySynchronize();   // wait for transpose output (PDL)
#endif

    tws[tid] = g_twN[2 * tid];

    const float sc = 1.0f / 256.0f;
    #pragma unroll
    for (int j = 0; j < 16; j++) {
        int k = tid + (j << 7);
        float2 Xk = __half22float2(X[k]);        // read 2x per block -> default policy
        float2 Xc = __half22float2(X[MH - k]);
        if (k == 0) { Xk.y = 0.f; Xc.y = 0.f; }
        float ex = sc * (Xk.x + Xc.x);
        float ey = sc * (Xk.y - Xc.y);
        float dx = sc * (Xk.x - Xc.x);
        float dy = sc * (Xk.y + Xc.y);
        float2 w = g_twN[k];
        float ox = dx * w.x - dy * w.y;
        float oy = dx * w.y + dy * w.x;
        buf[SW(k)] = make_float2(ex - oy, ey + ox);
    }
    __syncthreads();

    radix16_pass(buf, tws, tid, 1);    // m = 1
    radix16_pass(buf, tws, tid, 16);   // m = 16

    // final radix-8 pass: m=256 -> single j-group, twiddle-free; fused window
    __half2* __restrict__ fr = (__half2*)(g_frames + (size_t)f * NFFT);
    #pragma unroll
    for (int h = 0; h < 2; h++) {
        int idx = tid + (h << 7);      // butterfly index in [0,256)
        float2 x0 = buf[SW(idx       )];
        float2 x1 = buf[SW(idx +  256)];
        float2 x2 = buf[SW(idx +  512)];
        float2 x3 = buf[SW(idx +  768)];
        float2 x4 = buf[SW(idx + 1024)];
        float2 x5 = buf[SW(idx + 1280)];
        float2 x6 = buf[SW(idx + 1536)];
        float2 x7 = buf[SW(idx + 1792)];

        float2 ta = cadd(x0, x4), tb = csub(x0, x4);
        float2 tc = cadd(x2, x6), td = cmuli(csub(x2, x6));
        float2 E0 = cadd(ta, tc), E1 = cadd(tb, td);
        float2 E2 = csub(ta, tc), E3 = csub(tb, td);
        float2 sa = cadd(x1, x5), sb = csub(x1, x5);
        float2 scc = cadd(x3, x7), sd = cmuli(csub(x3, x7));
        float2 O0 = cadd(sa, scc), O1 = cadd(sb, sd);
        float2 O2 = csub(sa, scc), O3 = csub(sb, sd);
        const float R = 0.70710678118654752440f;
        O1 = make_float2(R*(O1.x - O1.y), R*(O1.x + O1.y));
        O2 = cmuli(O2);
        O3 = make_float2(R*(-O3.x - O3.y), R*(O3.x - O3.y));

        float2 y[8];
        y[0] = cadd(E0, O0); y[4] = csub(E0, O0);
        y[1] = cadd(E1, O1); y[5] = csub(E1, O1);
        y[2] = cadd(E2, O2); y[6] = csub(E2, O2);
        y[3] = cadd(E3, O3); y[7] = csub(E3, O3);

        #pragma unroll
        for (int q = 0; q < 8; q++) {
            int n = idx + (q << 8);
            float2 w = g_win[n];
            fr[n] = __floats2half2_rn(y[q].x * w.x, y[q].y * w.y);
        }
    }
}

// ---------------- gather overlap-add (fp16 frames -> fp32), 8 samples/thread -
__global__ void __launch_bounds__(128) ola_kernel(const float* __restrict__ wsi,
                                                  float* __restrict__ out, int outlen)
{
    int s = blockIdx.x;                // 1024-sample output segment
    int b = blockIdx.y;
    int r = threadIdx.x << 3;          // 0..1016, 8 halves (16B) per thread
    int j = (s << 10) + r;
    if (j + 8 > outlen) return;        // outlen divisible by 8 -> exact cover
    int p   = j + MH;                  // position in padded signal (skip N/2)
    int seg = p >> 10;                 // = s + 2

    // wsi is shared across all 8 batch rows -> default policy (L2 reuse)
    float4 w0 = *(const float4*)(wsi + p);
    float4 w1 = *(const float4*)(wsi + p + 4);

#if __CUDA_ARCH__ >= 900
    cudaGridDependencySynchronize();   // wait for ifft frames (PDL)
#endif

    const __half* frbase = g_frames + (size_t)b * TFR * NFFT;
    float acc[8] = {0,0,0,0,0,0,0,0};
    #pragma unroll
    for (int d = 0; d < 4; d++) {
        int t = seg - d;
        if (t >= 0 && t < TFR) {
            // each frames element consumed exactly once grid-wide -> evict-first
            uint4 raw = __ldcs((const uint4*)(frbase + (size_t)t * NFFT + r + (d << 10)));
            float2 v;
            v = __half22float2(*(__half2*)&raw.x); acc[0] += v.x; acc[1] += v.y;
            v = __half22float2(*(__half2*)&raw.y); acc[2] += v.x; acc[3] += v.y;
            v = __half22float2(*(__half2*)&raw.z); acc[4] += v.x; acc[5] += v.y;
            v = __half22float2(*(__half2*)&raw.w); acc[6] += v.x; acc[7] += v.y;
        }
    }
    float* op = out + (size_t)b * outlen + j;
    float4 o0 = make_float4(acc[0]*w0.x, acc[1]*w0.y, acc[2]*w0.z, acc[3]*w0.w);
    float4 o1 = make_float4(acc[4]*w1.x, acc[5]*w1.y, acc[6]*w1.z, acc[7]*w1.w);
    __stcs((float4*)(op),     o0);     // streaming store: out is never re-read
    __stcs((float4*)(op + 4), o1);
}

// ---------------- launch -----------------------------------------------------
extern "C" void kernel_launch(void* const* d_in, const int* in_sizes, int n_in,
                              void* d_out, int out_size)
{
    const float* re  = (const float*)d_in[0];
    const float* im  = (const float*)d_in[1];
    // d_in[2] = inverse_basis (unused: replaced analytically by the iFFT)
    const float* wsi = (const float*)d_in[3];
    float* out = (float*)d_out;
    int outlen = out_size / BATCH;     // 352800

    dim3 tgrid((CH + 31) / 32, (TFR + 63) / 64, BATCH);
    transpose_kernel<<<tgrid, dim3(32, 8)>>>(re, im);

    cudaLaunchAttribute attr[1];
    attr[0].id = cudaLaunchAttributeProgrammaticStreamSerialization;
    attr[0].val.programmaticStreamSerializationAllowed = 1;

    cudaLaunchConfig_t cfg1 = {};
    cfg1.gridDim = dim3(NFRAMES); cfg1.blockDim = dim3(128);
    cfg1.dynamicSmemBytes = 0; cfg1.stream = 0;
    cfg1.attrs = attr; cfg1.numAttrs = 1;
    if (cudaLaunchKernelEx(&cfg1, ifft_kernel) != cudaSuccess)
        ifft_kernel<<<NFRAMES, 128>>>();

    cudaLaunchConfig_t cfg2 = {};
    cfg2.gridDim = dim3((outlen + 1023) / 1024, BATCH); cfg2.blockDim = dim3(128);
    cfg2.dynamicSmemBytes = 0; cfg2.stream = 0;
    cfg2.attrs = attr; cfg2.numAttrs = 1;
    if (cudaLaunchKernelEx(&cfg2, ola_kernel, wsi, out, outlen) != cudaSuccess)
        ola_kernel<<<dim3((outlen + 1023) / 1024, BATCH), 128>>>(wsi, out, outlen);
}